// round 10
// baseline (speedup 1.0000x reference)
#include <cuda_runtime.h>
#include <cuda_fp16.h>
#include <stdint.h>

#define N_NODES_MAX 100000
#define N_EDGES_MAX 3200000
#define D_IN 256
#define D_OUT 256
#define ROW_CAP 96              // Poisson(32) rows; P(any>96) ~ 1e-13
#define OF_CAP 4096             // overflow side-list (expected empty)

#if defined(CUDA_API_PER_THREAD_DEFAULT_STREAM) || defined(__CUDA_API_PER_THREAD_DEFAULT_STREAM__)
#define DEF_STREAM cudaStreamPerThread
#else
#define DEF_STREAM cudaStreamLegacy
#endif

// ---------------------------------------------------------------------------
// Static device scratch
// ---------------------------------------------------------------------------
__device__ __half g_support_h[(size_t)N_NODES_MAX * D_OUT];      // 51.2 MB
__device__ uint2  g_edges[(size_t)N_NODES_MAX * ROW_CAP];        // 76.8 MB
__device__ int    g_cursor[N_NODES_MAX];
__device__ int    g_of_row[OF_CAP];
__device__ int    g_of_col[OF_CAP];
__device__ float  g_of_val[OF_CAP];
__device__ int    g_oflow_n;
__device__ int    g_idx64;

// ---------------------------------------------------------------------------
// Fused: zero cursors/overflow counter + index dtype detection (block 0)
// ---------------------------------------------------------------------------
__global__ void detect_zero_kernel(const unsigned int* __restrict__ words, int n) {
    int i = blockIdx.x * blockDim.x + threadIdx.x;
    if (i < n) g_cursor[i] = 0;
    if (i == 0) g_oflow_n = 0;
    if (blockIdx.x == 0) {
        __shared__ int any_nonzero;
        if (threadIdx.x == 0) any_nonzero = 0;
        __syncthreads();
        int local = 0;
        for (int k = threadIdx.x; k < 2048; k += blockDim.x)
            if (words[2 * k + 1] != 0u) local = 1;
        if (local) atomicOr(&any_nonzero, 1);
        __syncthreads();
        if (threadIdx.x == 0) g_idx64 = any_nonzero ? 0 : 1;
    }
}

__device__ __forceinline__ int load_idx(const void* p, int i) {
    return g_idx64 ? (int)((const long long*)p)[i] : ((const int*)p)[i];
}

// ---------------------------------------------------------------------------
// tf32 tensor-core GEMM over a 128-column slice of W, 2-stage cp.async
// pipeline. A streamed with L2 evict_first (protects the fp16 support table).
// ---------------------------------------------------------------------------
#define GM 128
#define GN 128
#define GK 32
#define AS_STRIDE 36
#define BS_STRIDE 136
#define ASZ (GM * AS_STRIDE)
#define BSZ (GK * BS_STRIDE)
#define GEMM_SMEM_BYTES ((2 * ASZ + 2 * BSZ) * 4)

__device__ __forceinline__ uint32_t smem_u32(const void* p) {
    return (uint32_t)__cvta_generic_to_shared(p);
}

__device__ __forceinline__ void cp16_evict_first(uint32_t dst, const void* src,
                                                 int src_bytes, uint64_t pol) {
    asm volatile(
        "cp.async.cg.shared.global.L2::cache_hint [%0], [%1], 16, %2, %3;"
        :: "r"(dst), "l"(src), "r"(src_bytes), "l"(pol));
}

__device__ __forceinline__ void cp16(uint32_t dst, const void* src) {
    asm volatile("cp.async.cg.shared.global [%0], [%1], 16;"
                 :: "r"(dst), "l"(src));
}

__device__ __forceinline__ uint32_t ld_tf32(const float* p) {
    uint32_t u;
    asm("cvt.rna.tf32.f32 %0, %1;" : "=r"(u) : "f"(*p));
    return u;
}

__global__ __launch_bounds__(256, 2) void gemm_tf32_kernel(
    const float* __restrict__ A, const float* __restrict__ W, int M, int bn0)
{
    extern __shared__ float smem[];
    float* As[2] = { smem,            smem + ASZ };
    float* Bs[2] = { smem + 2 * ASZ,  smem + 2 * ASZ + BSZ };

    uint64_t pol;
    asm("createpolicy.fractional.L2::evict_first.b64 %0, 1.0;" : "=l"(pol));

    const int tid  = threadIdx.x;
    const int wid  = tid >> 5;
    const int lane = tid & 31;
    const int g    = lane >> 2;
    const int tg   = lane & 3;
    const int warp_m = (wid & 3) * 32;
    const int warp_n = (wid >> 2) * 64;
    const int bm = blockIdx.y * GM;
    const int bn = bn0;

    float c[2][8][4];
    #pragma unroll
    for (int mi = 0; mi < 2; mi++)
        #pragma unroll
        for (int ni = 0; ni < 8; ni++)
            #pragma unroll
            for (int r = 0; r < 4; r++) c[mi][ni][r] = 0.0f;

    auto issue_tile = [&](int k0, int buf) {
        #pragma unroll
        for (int l = 0; l < 4; l++) {
            int idx = tid + l * 256;
            int row = idx >> 3, c4 = idx & 7;
            int m = bm + row;
            int mc = (m < M) ? m : (M - 1);
            cp16_evict_first(
                smem_u32(As[buf] + row * AS_STRIDE + c4 * 4),
                A + (size_t)mc * D_IN + k0 + c4 * 4,
                (m < M) ? 16 : 0, pol);
        }
        #pragma unroll
        for (int l = 0; l < 4; l++) {
            int idx = tid + l * 256;
            int row = idx >> 5, c4 = idx & 31;
            cp16(smem_u32(Bs[buf] + row * BS_STRIDE + c4 * 4),
                 W + (size_t)(k0 + row) * D_OUT + bn + c4 * 4);
        }
        asm volatile("cp.async.commit_group;");
    };

    issue_tile(0, 0);

    #pragma unroll
    for (int t = 0; t < D_IN / GK; t++) {
        if (t + 1 < D_IN / GK) {
            issue_tile((t + 1) * GK, (t + 1) & 1);
            asm volatile("cp.async.wait_group 1;");
        } else {
            asm volatile("cp.async.wait_group 0;");
        }
        __syncthreads();

        const float* as = As[t & 1];
        const float* bs = Bs[t & 1];
        #pragma unroll
        for (int ks = 0; ks < 4; ks++) {
            const int kb = ks * 8;
            uint32_t a[2][4], b[8][2];
            #pragma unroll
            for (int mi = 0; mi < 2; mi++) {
                int r = warp_m + mi * 16;
                a[mi][0] = ld_tf32(&as[(r + g)     * AS_STRIDE + kb + tg]);
                a[mi][1] = ld_tf32(&as[(r + g + 8) * AS_STRIDE + kb + tg]);
                a[mi][2] = ld_tf32(&as[(r + g)     * AS_STRIDE + kb + tg + 4]);
                a[mi][3] = ld_tf32(&as[(r + g + 8) * AS_STRIDE + kb + tg + 4]);
            }
            #pragma unroll
            for (int ni = 0; ni < 8; ni++) {
                int col = warp_n + ni * 8 + g;
                b[ni][0] = ld_tf32(&bs[(kb + tg)     * BS_STRIDE + col]);
                b[ni][1] = ld_tf32(&bs[(kb + tg + 4) * BS_STRIDE + col]);
            }
            #pragma unroll
            for (int mi = 0; mi < 2; mi++)
                #pragma unroll
                for (int ni = 0; ni < 8; ni++) {
                    asm volatile(
                        "mma.sync.aligned.m16n8k8.row.col.f32.tf32.tf32.f32 "
                        "{%0,%1,%2,%3}, {%4,%5,%6,%7}, {%8,%9}, {%0,%1,%2,%3};\n"
                        : "+f"(c[mi][ni][0]), "+f"(c[mi][ni][1]),
                          "+f"(c[mi][ni][2]), "+f"(c[mi][ni][3])
                        : "r"(a[mi][0]), "r"(a[mi][1]), "r"(a[mi][2]), "r"(a[mi][3]),
                          "r"(b[ni][0]), "r"(b[ni][1]));
                }
        }
        __syncthreads();
    }

    #pragma unroll
    for (int mi = 0; mi < 2; mi++) {
        int r0 = bm + warp_m + mi * 16 + g;
        #pragma unroll
        for (int ni = 0; ni < 8; ni++) {
            int col = bn + warp_n + ni * 8 + tg * 2;
            if (r0 < M)
                *(__half2*)(g_support_h + (size_t)r0 * D_OUT + col) =
                    __floats2half2_rn(c[mi][ni][0], c[mi][ni][1]);
            if (r0 + 8 < M)
                *(__half2*)(g_support_h + (size_t)(r0 + 8) * D_OUT + col) =
                    __floats2half2_rn(c[mi][ni][2], c[mi][ni][3]);
        }
    }
}

// ---------------------------------------------------------------------------
// Direct bucketing: g_edges[r*ROW_CAP + cursor++] = {col, val}.
// No hist, no scan. Overflow (P ~ 1e-13) goes to an exact side-list.
// ---------------------------------------------------------------------------
__global__ void bucket_kernel(const void* __restrict__ adj_row,
                              const void* __restrict__ adj_col,
                              const float* __restrict__ adj_val, int n_edges)
{
    int base = (blockIdx.x * blockDim.x + threadIdx.x) * 4;
    #pragma unroll
    for (int k = 0; k < 4; k++) {
        int e = base + k;
        if (e < n_edges) {
            int r = load_idx(adj_row, e);
            int c = load_idx(adj_col, e);
            float v = adj_val[e];
            int pos = atomicAdd(&g_cursor[r], 1);
            if (pos < ROW_CAP) {
                g_edges[(size_t)r * ROW_CAP + pos] =
                    make_uint2((unsigned)c, __float_as_uint(v));
            } else {
                int j = atomicAdd(&g_oflow_n, 1);
                if (j < OF_CAP) {
                    g_of_row[j] = r; g_of_col[j] = c; g_of_val[j] = v;
                }
            }
        }
    }
}

// ---------------------------------------------------------------------------
// Row accumulate over a 128-column slice (coff = 0 or 128). Also folds in
// the (expected-empty) overflow list for exactness.
// ---------------------------------------------------------------------------
__device__ __forceinline__ void acc_half4(float* acc, uint2 h, float v) {
    float2 f;
    f = __half22float2(*(__half2*)&h.x); acc[0] += v * f.x; acc[1] += v * f.y;
    f = __half22float2(*(__half2*)&h.y); acc[2] += v * f.x; acc[3] += v * f.y;
}

__global__ __launch_bounds__(256) void rowacc_kernel(float* __restrict__ out,
                                                     int n_nodes, int coff)
{
    const int sub  = threadIdx.x >> 5;
    const int lane = threadIdx.x & 31;
    const int row  = blockIdx.x * 8 + sub;
    if (row >= n_nodes) return;

    int cnt = g_cursor[row];
    if (cnt > ROW_CAP) cnt = ROW_CAP;
    const int s = row * ROW_CAP;
    const int e = s + cnt;

    float acc0[4], acc1[4];
    #pragma unroll
    for (int k = 0; k < 4; k++) { acc0[k] = 0.f; acc1[k] = 0.f; }

    int i = s;
    for (; i + 3 < e; i += 4) {
        uint2 e0 = __ldg(&g_edges[i]);
        uint2 e1 = __ldg(&g_edges[i + 1]);
        uint2 e2 = __ldg(&g_edges[i + 2]);
        uint2 e3 = __ldg(&g_edges[i + 3]);
        uint2 h0 = __ldg((const uint2*)(g_support_h + (size_t)e0.x * D_OUT + coff) + lane);
        uint2 h1 = __ldg((const uint2*)(g_support_h + (size_t)e1.x * D_OUT + coff) + lane);
        uint2 h2 = __ldg((const uint2*)(g_support_h + (size_t)e2.x * D_OUT + coff) + lane);
        uint2 h3 = __ldg((const uint2*)(g_support_h + (size_t)e3.x * D_OUT + coff) + lane);

        acc_half4(acc0, h0, __uint_as_float(e0.y));
        acc_half4(acc1, h1, __uint_as_float(e1.y));
        acc_half4(acc0, h2, __uint_as_float(e2.y));
        acc_half4(acc1, h3, __uint_as_float(e3.y));
    }
    for (; i < e; i++) {
        uint2 e0 = __ldg(&g_edges[i]);
        uint2 h0 = __ldg((const uint2*)(g_support_h + (size_t)e0.x * D_OUT + coff) + lane);
        acc_half4(acc0, h0, __uint_as_float(e0.y));
    }

    // Overflow fixup (expected n_of = 0; broadcast loads, negligible)
    int n_of = g_oflow_n;
    if (n_of > OF_CAP) n_of = OF_CAP;
    for (int j = 0; j < n_of; j++) {
        if (g_of_row[j] == row) {
            uint2 h = __ldg((const uint2*)(g_support_h +
                            (size_t)g_of_col[j] * D_OUT + coff) + lane);
            acc_half4(acc0, h, g_of_val[j]);
        }
    }

    float4 r4;
    r4.x = fmaxf(acc0[0] + acc1[0], 0.f);
    r4.y = fmaxf(acc0[1] + acc1[1], 0.f);
    r4.z = fmaxf(acc0[2] + acc1[2], 0.f);
    r4.w = fmaxf(acc0[3] + acc1[3], 0.f);
    __stcs((float4*)(out + (size_t)row * D_OUT + coff) + lane, r4);
}

// ---------------------------------------------------------------------------
// Launch:
//   S0: GEMM-A (t=0) -> GEMM-B -> rowaccB ;  S2: detect+zero -> bucket ;
//   S3 (high prio): rowaccA (waits GEMM-A + bucket)
// ---------------------------------------------------------------------------
extern "C" void kernel_launch(void* const* d_in, const int* in_sizes, int n_in,
                              void* d_out, int out_size)
{
    static cudaStream_t s2 = nullptr, s3 = nullptr;
    static cudaEvent_t ev_fork = nullptr, ev_csr = nullptr,
                       ev_ga = nullptr, ev_ra = nullptr;
    static bool tried = false;
    if (!tried) {
        tried = true;
        int lo = 0, hi = 0;
        cudaDeviceGetStreamPriorityRange(&lo, &hi);
        bool ok = cudaStreamCreateWithPriority(&s2, cudaStreamNonBlocking, 0) == cudaSuccess
               && cudaStreamCreateWithPriority(&s3, cudaStreamNonBlocking, hi) == cudaSuccess
               && cudaEventCreateWithFlags(&ev_fork, cudaEventDisableTiming) == cudaSuccess
               && cudaEventCreateWithFlags(&ev_csr,  cudaEventDisableTiming) == cudaSuccess
               && cudaEventCreateWithFlags(&ev_ga,   cudaEventDisableTiming) == cudaSuccess
               && cudaEventCreateWithFlags(&ev_ra,   cudaEventDisableTiming) == cudaSuccess;
        if (!ok) s2 = nullptr;
        cudaFuncSetAttribute(gemm_tf32_kernel,
                             cudaFuncAttributeMaxDynamicSharedMemorySize,
                             GEMM_SMEM_BYTES);
    }
    const bool par = (s2 != nullptr);
    cudaStream_t cs = par ? s2 : DEF_STREAM;

    const float* features = (const float*)d_in[0];
    const float* weight   = (const float*)d_in[1];
    const void*  adj_row  = d_in[2];
    const void*  adj_col  = d_in[3];
    const float* adj_val  = (const float*)d_in[4];
    float* out = (float*)d_out;

    const int n_nodes = in_sizes[0] / D_IN;
    const int n_edges = in_sizes[4];

    if (par) {
        cudaEventRecord(ev_fork, DEF_STREAM);
        cudaStreamWaitEvent(s2, ev_fork, 0);
    }

    // --- S2: detect + zero cursors, then direct bucketing ---
    detect_zero_kernel<<<(n_nodes + 255) / 256, 256, 0, cs>>>(
        (const unsigned int*)adj_row, n_nodes);
    bucket_kernel<<<(n_edges + 1023) / 1024, 256, 0, cs>>>(adj_row, adj_col,
                                                           adj_val, n_edges);
    if (par) cudaEventRecord(ev_csr, s2);

    // --- S0: GEMM-A (support cols 0-127), starts immediately ---
    dim3 ggrid(1, (n_nodes + GM - 1) / GM);
    gemm_tf32_kernel<<<ggrid, 256, GEMM_SMEM_BYTES>>>(features, weight,
                                                      n_nodes, 0);
    if (par) cudaEventRecord(ev_ga, DEF_STREAM);

    // --- S3 (high priority): rowaccA after GEMM-A + bucket ---
    if (par) {
        cudaStreamWaitEvent(s3, ev_ga, 0);
        cudaStreamWaitEvent(s3, ev_csr, 0);
    } else {
        gemm_tf32_kernel<<<ggrid, 256, GEMM_SMEM_BYTES>>>(features, weight,
                                                          n_nodes, 128);
    }
    rowacc_kernel<<<(n_nodes + 7) / 8, 256, 0, par ? s3 : DEF_STREAM>>>(
        out, n_nodes, 0);
    if (par) cudaEventRecord(ev_ra, s3);

    // --- S0: GEMM-B (support cols 128-255), concurrent with rowaccA ---
    if (par) gemm_tf32_kernel<<<ggrid, 256, GEMM_SMEM_BYTES>>>(features, weight,
                                                               n_nodes, 128);

    // --- S0: rowaccB after GEMM-B (+bucket) ---
    if (par) cudaStreamWaitEvent(DEF_STREAM, ev_csr, 0);
    rowacc_kernel<<<(n_nodes + 7) / 8, 256>>>(out, n_nodes, 128);

    if (par) cudaStreamWaitEvent(DEF_STREAM, ev_ra, 0);
}

// round 11
// speedup vs baseline: 1.1137x; 1.1137x over previous
#include <cuda_runtime.h>
#include <cuda_fp16.h>
#include <stdint.h>

#define N_NODES_MAX 100000
#define N_EDGES_MAX 3200000
#define D_IN 256
#define D_OUT 256
#define ROW_CAP 64              // Poisson(32); P(row>64) ~ 2e-6 -> ~0 overflows
#define OF_CAP 4096             // exact overflow side-list

#if defined(CUDA_API_PER_THREAD_DEFAULT_STREAM) || defined(__CUDA_API_PER_THREAD_DEFAULT_STREAM__)
#define DEF_STREAM cudaStreamPerThread
#else
#define DEF_STREAM cudaStreamLegacy
#endif

// ---------------------------------------------------------------------------
// Static device scratch
// ---------------------------------------------------------------------------
__device__ __half g_support_h[(size_t)N_NODES_MAX * D_OUT];      // 51.2 MB
__device__ uint2  g_edges[(size_t)N_NODES_MAX * ROW_CAP];        // 51.2 MB
__device__ int    g_cursor[N_NODES_MAX];
__device__ int    g_of_row[OF_CAP];
__device__ int    g_of_col[OF_CAP];
__device__ float  g_of_val[OF_CAP];
__device__ int    g_oflow_n;
__device__ int    g_idx64;

// ---------------------------------------------------------------------------
// Fused: zero cursors/overflow counter + index dtype detection (block 0)
// ---------------------------------------------------------------------------
__global__ void detect_zero_kernel(const unsigned int* __restrict__ words, int n) {
    int i = blockIdx.x * blockDim.x + threadIdx.x;
    if (i < n) g_cursor[i] = 0;
    if (i == 0) g_oflow_n = 0;
    if (blockIdx.x == 0) {
        __shared__ int any_nonzero;
        if (threadIdx.x == 0) any_nonzero = 0;
        __syncthreads();
        int local = 0;
        for (int k = threadIdx.x; k < 2048; k += blockDim.x)
            if (words[2 * k + 1] != 0u) local = 1;
        if (local) atomicOr(&any_nonzero, 1);
        __syncthreads();
        if (threadIdx.x == 0) g_idx64 = any_nonzero ? 0 : 1;
    }
}

__device__ __forceinline__ int load_idx(const void* p, int i) {
    return g_idx64 ? (int)((const long long*)p)[i] : ((const int*)p)[i];
}

// ---------------------------------------------------------------------------
// tf32 tensor-core GEMM over a 128-column slice of W, 2-stage cp.async
// pipeline. A streamed with L2 evict_first (protects the fp16 support table).
// ---------------------------------------------------------------------------
#define GM 128
#define GN 128
#define GK 32
#define AS_STRIDE 36
#define BS_STRIDE 136
#define ASZ (GM * AS_STRIDE)
#define BSZ (GK * BS_STRIDE)
#define GEMM_SMEM_BYTES ((2 * ASZ + 2 * BSZ) * 4)

__device__ __forceinline__ uint32_t smem_u32(const void* p) {
    return (uint32_t)__cvta_generic_to_shared(p);
}

__device__ __forceinline__ void cp16_evict_first(uint32_t dst, const void* src,
                                                 int src_bytes, uint64_t pol) {
    asm volatile(
        "cp.async.cg.shared.global.L2::cache_hint [%0], [%1], 16, %2, %3;"
        :: "r"(dst), "l"(src), "r"(src_bytes), "l"(pol));
}

__device__ __forceinline__ void cp16(uint32_t dst, const void* src) {
    asm volatile("cp.async.cg.shared.global [%0], [%1], 16;"
                 :: "r"(dst), "l"(src));
}

__device__ __forceinline__ uint32_t ld_tf32(const float* p) {
    uint32_t u;
    asm("cvt.rna.tf32.f32 %0, %1;" : "=r"(u) : "f"(*p));
    return u;
}

__global__ __launch_bounds__(256, 2) void gemm_tf32_kernel(
    const float* __restrict__ A, const float* __restrict__ W, int M, int bn0)
{
    extern __shared__ float smem[];
    float* As[2] = { smem,            smem + ASZ };
    float* Bs[2] = { smem + 2 * ASZ,  smem + 2 * ASZ + BSZ };

    uint64_t pol;
    asm("createpolicy.fractional.L2::evict_first.b64 %0, 1.0;" : "=l"(pol));

    const int tid  = threadIdx.x;
    const int wid  = tid >> 5;
    const int lane = tid & 31;
    const int g    = lane >> 2;
    const int tg   = lane & 3;
    const int warp_m = (wid & 3) * 32;
    const int warp_n = (wid >> 2) * 64;
    const int bm = blockIdx.y * GM;
    const int bn = bn0;

    float c[2][8][4];
    #pragma unroll
    for (int mi = 0; mi < 2; mi++)
        #pragma unroll
        for (int ni = 0; ni < 8; ni++)
            #pragma unroll
            for (int r = 0; r < 4; r++) c[mi][ni][r] = 0.0f;

    auto issue_tile = [&](int k0, int buf) {
        #pragma unroll
        for (int l = 0; l < 4; l++) {
            int idx = tid + l * 256;
            int row = idx >> 3, c4 = idx & 7;
            int m = bm + row;
            int mc = (m < M) ? m : (M - 1);
            cp16_evict_first(
                smem_u32(As[buf] + row * AS_STRIDE + c4 * 4),
                A + (size_t)mc * D_IN + k0 + c4 * 4,
                (m < M) ? 16 : 0, pol);
        }
        #pragma unroll
        for (int l = 0; l < 4; l++) {
            int idx = tid + l * 256;
            int row = idx >> 5, c4 = idx & 31;
            cp16(smem_u32(Bs[buf] + row * BS_STRIDE + c4 * 4),
                 W + (size_t)(k0 + row) * D_OUT + bn + c4 * 4);
        }
        asm volatile("cp.async.commit_group;");
    };

    issue_tile(0, 0);

    #pragma unroll
    for (int t = 0; t < D_IN / GK; t++) {
        if (t + 1 < D_IN / GK) {
            issue_tile((t + 1) * GK, (t + 1) & 1);
            asm volatile("cp.async.wait_group 1;");
        } else {
            asm volatile("cp.async.wait_group 0;");
        }
        __syncthreads();

        const float* as = As[t & 1];
        const float* bs = Bs[t & 1];
        #pragma unroll
        for (int ks = 0; ks < 4; ks++) {
            const int kb = ks * 8;
            uint32_t a[2][4], b[8][2];
            #pragma unroll
            for (int mi = 0; mi < 2; mi++) {
                int r = warp_m + mi * 16;
                a[mi][0] = ld_tf32(&as[(r + g)     * AS_STRIDE + kb + tg]);
                a[mi][1] = ld_tf32(&as[(r + g + 8) * AS_STRIDE + kb + tg]);
                a[mi][2] = ld_tf32(&as[(r + g)     * AS_STRIDE + kb + tg + 4]);
                a[mi][3] = ld_tf32(&as[(r + g + 8) * AS_STRIDE + kb + tg + 4]);
            }
            #pragma unroll
            for (int ni = 0; ni < 8; ni++) {
                int col = warp_n + ni * 8 + g;
                b[ni][0] = ld_tf32(&bs[(kb + tg)     * BS_STRIDE + col]);
                b[ni][1] = ld_tf32(&bs[(kb + tg + 4) * BS_STRIDE + col]);
            }
            #pragma unroll
            for (int mi = 0; mi < 2; mi++)
                #pragma unroll
                for (int ni = 0; ni < 8; ni++) {
                    asm volatile(
                        "mma.sync.aligned.m16n8k8.row.col.f32.tf32.tf32.f32 "
                        "{%0,%1,%2,%3}, {%4,%5,%6,%7}, {%8,%9}, {%0,%1,%2,%3};\n"
                        : "+f"(c[mi][ni][0]), "+f"(c[mi][ni][1]),
                          "+f"(c[mi][ni][2]), "+f"(c[mi][ni][3])
                        : "r"(a[mi][0]), "r"(a[mi][1]), "r"(a[mi][2]), "r"(a[mi][3]),
                          "r"(b[ni][0]), "r"(b[ni][1]));
                }
        }
        __syncthreads();
    }

    #pragma unroll
    for (int mi = 0; mi < 2; mi++) {
        int r0 = bm + warp_m + mi * 16 + g;
        #pragma unroll
        for (int ni = 0; ni < 8; ni++) {
            int col = bn + warp_n + ni * 8 + tg * 2;
            if (r0 < M)
                *(__half2*)(g_support_h + (size_t)r0 * D_OUT + col) =
                    __floats2half2_rn(c[mi][ni][0], c[mi][ni][1]);
            if (r0 + 8 < M)
                *(__half2*)(g_support_h + (size_t)(r0 + 8) * D_OUT + col) =
                    __floats2half2_rn(c[mi][ni][2], c[mi][ni][3]);
        }
    }
}

// ---------------------------------------------------------------------------
// Direct bucketing, COALESCED: one edge per thread (consecutive threads read
// consecutive edges). g_edges[r*ROW_CAP + cursor++] = {col, val}.
// ---------------------------------------------------------------------------
__global__ void bucket_kernel(const void* __restrict__ adj_row,
                              const void* __restrict__ adj_col,
                              const float* __restrict__ adj_val, int n_edges)
{
    int e = blockIdx.x * blockDim.x + threadIdx.x;
    if (e >= n_edges) return;
    int r = load_idx(adj_row, e);
    int c = load_idx(adj_col, e);
    float v = adj_val[e];
    int pos = atomicAdd(&g_cursor[r], 1);
    if (pos < ROW_CAP) {
        g_edges[(size_t)r * ROW_CAP + pos] =
            make_uint2((unsigned)c, __float_as_uint(v));
    } else {
        int j = atomicAdd(&g_oflow_n, 1);
        if (j < OF_CAP) {
            g_of_row[j] = r; g_of_col[j] = c; g_of_val[j] = v;
        }
    }
}

// ---------------------------------------------------------------------------
// Row accumulate over a 128-column slice (coff = 0 or 128) + overflow fixup.
// ---------------------------------------------------------------------------
__device__ __forceinline__ void acc_half4(float* acc, uint2 h, float v) {
    float2 f;
    f = __half22float2(*(__half2*)&h.x); acc[0] += v * f.x; acc[1] += v * f.y;
    f = __half22float2(*(__half2*)&h.y); acc[2] += v * f.x; acc[3] += v * f.y;
}

__global__ __launch_bounds__(256) void rowacc_kernel(float* __restrict__ out,
                                                     int n_nodes, int coff)
{
    const int sub  = threadIdx.x >> 5;
    const int lane = threadIdx.x & 31;
    const int row  = blockIdx.x * 8 + sub;
    if (row >= n_nodes) return;

    int cnt = g_cursor[row];
    if (cnt > ROW_CAP) cnt = ROW_CAP;
    const int s = row * ROW_CAP;
    const int e = s + cnt;

    float acc0[4], acc1[4];
    #pragma unroll
    for (int k = 0; k < 4; k++) { acc0[k] = 0.f; acc1[k] = 0.f; }

    int i = s;
    for (; i + 3 < e; i += 4) {
        uint2 e0 = __ldg(&g_edges[i]);
        uint2 e1 = __ldg(&g_edges[i + 1]);
        uint2 e2 = __ldg(&g_edges[i + 2]);
        uint2 e3 = __ldg(&g_edges[i + 3]);
        uint2 h0 = __ldg((const uint2*)(g_support_h + (size_t)e0.x * D_OUT + coff) + lane);
        uint2 h1 = __ldg((const uint2*)(g_support_h + (size_t)e1.x * D_OUT + coff) + lane);
        uint2 h2 = __ldg((const uint2*)(g_support_h + (size_t)e2.x * D_OUT + coff) + lane);
        uint2 h3 = __ldg((const uint2*)(g_support_h + (size_t)e3.x * D_OUT + coff) + lane);

        acc_half4(acc0, h0, __uint_as_float(e0.y));
        acc_half4(acc1, h1, __uint_as_float(e1.y));
        acc_half4(acc0, h2, __uint_as_float(e2.y));
        acc_half4(acc1, h3, __uint_as_float(e3.y));
    }
    for (; i < e; i++) {
        uint2 e0 = __ldg(&g_edges[i]);
        uint2 h0 = __ldg((const uint2*)(g_support_h + (size_t)e0.x * D_OUT + coff) + lane);
        acc_half4(acc0, h0, __uint_as_float(e0.y));
    }

    // Overflow fixup (expected 0-1 entries total)
    int n_of = g_oflow_n;
    if (n_of > OF_CAP) n_of = OF_CAP;
    for (int j = 0; j < n_of; j++) {
        if (g_of_row[j] == row) {
            uint2 h = __ldg((const uint2*)(g_support_h +
                            (size_t)g_of_col[j] * D_OUT + coff) + lane);
            acc_half4(acc0, h, g_of_val[j]);
        }
    }

    float4 r4;
    r4.x = fmaxf(acc0[0] + acc1[0], 0.f);
    r4.y = fmaxf(acc0[1] + acc1[1], 0.f);
    r4.z = fmaxf(acc0[2] + acc1[2], 0.f);
    r4.w = fmaxf(acc0[3] + acc1[3], 0.f);
    __stcs((float4*)(out + (size_t)row * D_OUT + coff) + lane, r4);
}

// ---------------------------------------------------------------------------
// Launch:
//   S0: GEMM-A (t=0) -> GEMM-B -> rowaccB ;  S2: detect+zero -> bucket ;
//   S3 (high prio): rowaccA (waits GEMM-A + bucket)
// ---------------------------------------------------------------------------
extern "C" void kernel_launch(void* const* d_in, const int* in_sizes, int n_in,
                              void* d_out, int out_size)
{
    static cudaStream_t s2 = nullptr, s3 = nullptr;
    static cudaEvent_t ev_fork = nullptr, ev_csr = nullptr,
                       ev_ga = nullptr, ev_ra = nullptr;
    static bool tried = false;
    if (!tried) {
        tried = true;
        int lo = 0, hi = 0;
        cudaDeviceGetStreamPriorityRange(&lo, &hi);
        bool ok = cudaStreamCreateWithPriority(&s2, cudaStreamNonBlocking, 0) == cudaSuccess
               && cudaStreamCreateWithPriority(&s3, cudaStreamNonBlocking, hi) == cudaSuccess
               && cudaEventCreateWithFlags(&ev_fork, cudaEventDisableTiming) == cudaSuccess
               && cudaEventCreateWithFlags(&ev_csr,  cudaEventDisableTiming) == cudaSuccess
               && cudaEventCreateWithFlags(&ev_ga,   cudaEventDisableTiming) == cudaSuccess
               && cudaEventCreateWithFlags(&ev_ra,   cudaEventDisableTiming) == cudaSuccess;
        if (!ok) s2 = nullptr;
        cudaFuncSetAttribute(gemm_tf32_kernel,
                             cudaFuncAttributeMaxDynamicSharedMemorySize,
                             GEMM_SMEM_BYTES);
    }
    const bool par = (s2 != nullptr);
    cudaStream_t cs = par ? s2 : DEF_STREAM;

    const float* features = (const float*)d_in[0];
    const float* weight   = (const float*)d_in[1];
    const void*  adj_row  = d_in[2];
    const void*  adj_col  = d_in[3];
    const float* adj_val  = (const float*)d_in[4];
    float* out = (float*)d_out;

    const int n_nodes = in_sizes[0] / D_IN;
    const int n_edges = in_sizes[4];

    if (par) {
        cudaEventRecord(ev_fork, DEF_STREAM);
        cudaStreamWaitEvent(s2, ev_fork, 0);
    }

    // --- S2: detect + zero cursors, then coalesced bucketing ---
    detect_zero_kernel<<<(n_nodes + 255) / 256, 256, 0, cs>>>(
        (const unsigned int*)adj_row, n_nodes);
    bucket_kernel<<<(n_edges + 255) / 256, 256, 0, cs>>>(adj_row, adj_col,
                                                         adj_val, n_edges);
    if (par) cudaEventRecord(ev_csr, s2);

    // --- S0: GEMM-A (support cols 0-127), starts immediately ---
    dim3 ggrid(1, (n_nodes + GM - 1) / GM);
    gemm_tf32_kernel<<<ggrid, 256, GEMM_SMEM_BYTES>>>(features, weight,
                                                      n_nodes, 0);
    if (par) cudaEventRecord(ev_ga, DEF_STREAM);

    // --- S3 (high priority): rowaccA after GEMM-A + bucket ---
    if (par) {
        cudaStreamWaitEvent(s3, ev_ga, 0);
        cudaStreamWaitEvent(s3, ev_csr, 0);
    } else {
        gemm_tf32_kernel<<<ggrid, 256, GEMM_SMEM_BYTES>>>(features, weight,
                                                          n_nodes, 128);
    }
    rowacc_kernel<<<(n_nodes + 7) / 8, 256, 0, par ? s3 : DEF_STREAM>>>(
        out, n_nodes, 0);
    if (par) cudaEventRecord(ev_ra, s3);

    // --- S0: GEMM-B (support cols 128-255), concurrent with rowaccA ---
    if (par) gemm_tf32_kernel<<<ggrid, 256, GEMM_SMEM_BYTES>>>(features, weight,
                                                               n_nodes, 128);

    // --- S0: rowaccB after GEMM-B (+bucket) ---
    if (par) cudaStreamWaitEvent(DEF_STREAM, ev_csr, 0);
    rowacc_kernel<<<(n_nodes + 7) / 8, 256>>>(out, n_nodes, 128);

    if (par) cudaStreamWaitEvent(DEF_STREAM, ev_ra, 0);
}

// round 12
// speedup vs baseline: 1.1170x; 1.0030x over previous
#include <cuda_runtime.h>
#include <cuda_fp16.h>
#include <stdint.h>

#define N_NODES_MAX 100000
#define N_EDGES_MAX 3200000
#define D_IN 256
#define D_OUT 256
#define ROW_CAP 64              // Poisson(32); P(row>64) ~ 2e-6 -> ~0 overflows
#define OF_CAP 4096             // exact overflow side-list

#if defined(CUDA_API_PER_THREAD_DEFAULT_STREAM) || defined(__CUDA_API_PER_THREAD_DEFAULT_STREAM__)
#define DEF_STREAM cudaStreamPerThread
#else
#define DEF_STREAM cudaStreamLegacy
#endif

// ---------------------------------------------------------------------------
// Static device scratch
// ---------------------------------------------------------------------------
__device__ __half g_support_h[(size_t)N_NODES_MAX * D_OUT];      // 51.2 MB
__device__ uint2  g_edges[(size_t)N_NODES_MAX * ROW_CAP];        // 51.2 MB
__device__ int    g_cursor[N_NODES_MAX];
__device__ int    g_of_row[OF_CAP];
__device__ int    g_of_col[OF_CAP];
__device__ float  g_of_val[OF_CAP];
__device__ int    g_oflow_n;
__device__ int    g_idx64;

// ---------------------------------------------------------------------------
// Fused: zero cursors/overflow counter + index dtype detection (block 0)
// ---------------------------------------------------------------------------
__global__ void detect_zero_kernel(const unsigned int* __restrict__ words, int n) {
    int i = blockIdx.x * blockDim.x + threadIdx.x;
    if (i < n) g_cursor[i] = 0;
    if (i == 0) g_oflow_n = 0;
    if (blockIdx.x == 0) {
        __shared__ int any_nonzero;
        if (threadIdx.x == 0) any_nonzero = 0;
        __syncthreads();
        int local = 0;
        for (int k = threadIdx.x; k < 2048; k += blockDim.x)
            if (words[2 * k + 1] != 0u) local = 1;
        if (local) atomicOr(&any_nonzero, 1);
        __syncthreads();
        if (threadIdx.x == 0) g_idx64 = any_nonzero ? 0 : 1;
    }
}

__device__ __forceinline__ int load_idx(const void* p, int i) {
    return g_idx64 ? (int)((const long long*)p)[i] : ((const int*)p)[i];
}

// ---------------------------------------------------------------------------
// tf32 tensor-core GEMM over a 128-column slice of W, 2-stage cp.async
// pipeline. A streamed with L2 evict_first (protects the fp16 support table).
// ---------------------------------------------------------------------------
#define GM 128
#define GN 128
#define GK 32
#define AS_STRIDE 36
#define BS_STRIDE 136
#define ASZ (GM * AS_STRIDE)
#define BSZ (GK * BS_STRIDE)
#define GEMM_SMEM_BYTES ((2 * ASZ + 2 * BSZ) * 4)

__device__ __forceinline__ uint32_t smem_u32(const void* p) {
    return (uint32_t)__cvta_generic_to_shared(p);
}

__device__ __forceinline__ void cp16_evict_first(uint32_t dst, const void* src,
                                                 int src_bytes, uint64_t pol) {
    asm volatile(
        "cp.async.cg.shared.global.L2::cache_hint [%0], [%1], 16, %2, %3;"
        :: "r"(dst), "l"(src), "r"(src_bytes), "l"(pol));
}

__device__ __forceinline__ void cp16(uint32_t dst, const void* src) {
    asm volatile("cp.async.cg.shared.global [%0], [%1], 16;"
                 :: "r"(dst), "l"(src));
}

__device__ __forceinline__ uint32_t ld_tf32(const float* p) {
    uint32_t u;
    asm("cvt.rna.tf32.f32 %0, %1;" : "=r"(u) : "f"(*p));
    return u;
}

__global__ __launch_bounds__(256, 2) void gemm_tf32_kernel(
    const float* __restrict__ A, const float* __restrict__ W, int M, int bn0)
{
    extern __shared__ float smem[];
    float* As[2] = { smem,            smem + ASZ };
    float* Bs[2] = { smem + 2 * ASZ,  smem + 2 * ASZ + BSZ };

    uint64_t pol;
    asm("createpolicy.fractional.L2::evict_first.b64 %0, 1.0;" : "=l"(pol));

    const int tid  = threadIdx.x;
    const int wid  = tid >> 5;
    const int lane = tid & 31;
    const int g    = lane >> 2;
    const int tg   = lane & 3;
    const int warp_m = (wid & 3) * 32;
    const int warp_n = (wid >> 2) * 64;
    const int bm = blockIdx.y * GM;
    const int bn = bn0;

    float c[2][8][4];
    #pragma unroll
    for (int mi = 0; mi < 2; mi++)
        #pragma unroll
        for (int ni = 0; ni < 8; ni++)
            #pragma unroll
            for (int r = 0; r < 4; r++) c[mi][ni][r] = 0.0f;

    auto issue_tile = [&](int k0, int buf) {
        #pragma unroll
        for (int l = 0; l < 4; l++) {
            int idx = tid + l * 256;
            int row = idx >> 3, c4 = idx & 7;
            int m = bm + row;
            int mc = (m < M) ? m : (M - 1);
            cp16_evict_first(
                smem_u32(As[buf] + row * AS_STRIDE + c4 * 4),
                A + (size_t)mc * D_IN + k0 + c4 * 4,
                (m < M) ? 16 : 0, pol);
        }
        #pragma unroll
        for (int l = 0; l < 4; l++) {
            int idx = tid + l * 256;
            int row = idx >> 5, c4 = idx & 31;
            cp16(smem_u32(Bs[buf] + row * BS_STRIDE + c4 * 4),
                 W + (size_t)(k0 + row) * D_OUT + bn + c4 * 4);
        }
        asm volatile("cp.async.commit_group;");
    };

    issue_tile(0, 0);

    #pragma unroll
    for (int t = 0; t < D_IN / GK; t++) {
        if (t + 1 < D_IN / GK) {
            issue_tile((t + 1) * GK, (t + 1) & 1);
            asm volatile("cp.async.wait_group 1;");
        } else {
            asm volatile("cp.async.wait_group 0;");
        }
        __syncthreads();

        const float* as = As[t & 1];
        const float* bs = Bs[t & 1];
        #pragma unroll
        for (int ks = 0; ks < 4; ks++) {
            const int kb = ks * 8;
            uint32_t a[2][4], b[8][2];
            #pragma unroll
            for (int mi = 0; mi < 2; mi++) {
                int r = warp_m + mi * 16;
                a[mi][0] = ld_tf32(&as[(r + g)     * AS_STRIDE + kb + tg]);
                a[mi][1] = ld_tf32(&as[(r + g + 8) * AS_STRIDE + kb + tg]);
                a[mi][2] = ld_tf32(&as[(r + g)     * AS_STRIDE + kb + tg + 4]);
                a[mi][3] = ld_tf32(&as[(r + g + 8) * AS_STRIDE + kb + tg + 4]);
            }
            #pragma unroll
            for (int ni = 0; ni < 8; ni++) {
                int col = warp_n + ni * 8 + g;
                b[ni][0] = ld_tf32(&bs[(kb + tg)     * BS_STRIDE + col]);
                b[ni][1] = ld_tf32(&bs[(kb + tg + 4) * BS_STRIDE + col]);
            }
            #pragma unroll
            for (int mi = 0; mi < 2; mi++)
                #pragma unroll
                for (int ni = 0; ni < 8; ni++) {
                    asm volatile(
                        "mma.sync.aligned.m16n8k8.row.col.f32.tf32.tf32.f32 "
                        "{%0,%1,%2,%3}, {%4,%5,%6,%7}, {%8,%9}, {%0,%1,%2,%3};\n"
                        : "+f"(c[mi][ni][0]), "+f"(c[mi][ni][1]),
                          "+f"(c[mi][ni][2]), "+f"(c[mi][ni][3])
                        : "r"(a[mi][0]), "r"(a[mi][1]), "r"(a[mi][2]), "r"(a[mi][3]),
                          "r"(b[ni][0]), "r"(b[ni][1]));
                }
        }
        __syncthreads();
    }

    #pragma unroll
    for (int mi = 0; mi < 2; mi++) {
        int r0 = bm + warp_m + mi * 16 + g;
        #pragma unroll
        for (int ni = 0; ni < 8; ni++) {
            int col = bn + warp_n + ni * 8 + tg * 2;
            if (r0 < M)
                *(__half2*)(g_support_h + (size_t)r0 * D_OUT + col) =
                    __floats2half2_rn(c[mi][ni][0], c[mi][ni][1]);
            if (r0 + 8 < M)
                *(__half2*)(g_support_h + (size_t)(r0 + 8) * D_OUT + col) =
                    __floats2half2_rn(c[mi][ni][2], c[mi][ni][3]);
        }
    }
}

// ---------------------------------------------------------------------------
// Direct bucketing, coalesced: one edge per thread.
// ---------------------------------------------------------------------------
__global__ void bucket_kernel(const void* __restrict__ adj_row,
                              const void* __restrict__ adj_col,
                              const float* __restrict__ adj_val, int n_edges)
{
    int e = blockIdx.x * blockDim.x + threadIdx.x;
    if (e >= n_edges) return;
    int r = load_idx(adj_row, e);
    int c = load_idx(adj_col, e);
    float v = adj_val[e];
    int pos = atomicAdd(&g_cursor[r], 1);
    if (pos < ROW_CAP) {
        g_edges[(size_t)r * ROW_CAP + pos] =
            make_uint2((unsigned)c, __float_as_uint(v));
    } else {
        int j = atomicAdd(&g_oflow_n, 1);
        if (j < OF_CAP) {
            g_of_row[j] = r; g_of_col[j] = c; g_of_val[j] = v;
        }
    }
}

// ---------------------------------------------------------------------------
// Row accumulate over a 128-column slice (coff = 0 or 128) + overflow fixup.
// ---------------------------------------------------------------------------
__device__ __forceinline__ void acc_half4(float* acc, uint2 h, float v) {
    float2 f;
    f = __half22float2(*(__half2*)&h.x); acc[0] += v * f.x; acc[1] += v * f.y;
    f = __half22float2(*(__half2*)&h.y); acc[2] += v * f.x; acc[3] += v * f.y;
}

__global__ __launch_bounds__(256) void rowacc_kernel(float* __restrict__ out,
                                                     int n_nodes, int coff)
{
    const int sub  = threadIdx.x >> 5;
    const int lane = threadIdx.x & 31;
    const int row  = blockIdx.x * 8 + sub;
    if (row >= n_nodes) return;

    int cnt = g_cursor[row];
    if (cnt > ROW_CAP) cnt = ROW_CAP;
    const int s = row * ROW_CAP;
    const int e = s + cnt;

    float acc0[4], acc1[4];
    #pragma unroll
    for (int k = 0; k < 4; k++) { acc0[k] = 0.f; acc1[k] = 0.f; }

    int i = s;
    for (; i + 3 < e; i += 4) {
        uint2 e0 = __ldg(&g_edges[i]);
        uint2 e1 = __ldg(&g_edges[i + 1]);
        uint2 e2 = __ldg(&g_edges[i + 2]);
        uint2 e3 = __ldg(&g_edges[i + 3]);
        uint2 h0 = __ldg((const uint2*)(g_support_h + (size_t)e0.x * D_OUT + coff) + lane);
        uint2 h1 = __ldg((const uint2*)(g_support_h + (size_t)e1.x * D_OUT + coff) + lane);
        uint2 h2 = __ldg((const uint2*)(g_support_h + (size_t)e2.x * D_OUT + coff) + lane);
        uint2 h3 = __ldg((const uint2*)(g_support_h + (size_t)e3.x * D_OUT + coff) + lane);

        acc_half4(acc0, h0, __uint_as_float(e0.y));
        acc_half4(acc1, h1, __uint_as_float(e1.y));
        acc_half4(acc0, h2, __uint_as_float(e2.y));
        acc_half4(acc1, h3, __uint_as_float(e3.y));
    }
    for (; i < e; i++) {
        uint2 e0 = __ldg(&g_edges[i]);
        uint2 h0 = __ldg((const uint2*)(g_support_h + (size_t)e0.x * D_OUT + coff) + lane);
        acc_half4(acc0, h0, __uint_as_float(e0.y));
    }

    // Overflow fixup (expected 0-1 entries total)
    int n_of = g_oflow_n;
    if (n_of > OF_CAP) n_of = OF_CAP;
    for (int j = 0; j < n_of; j++) {
        if (g_of_row[j] == row) {
            uint2 h = __ldg((const uint2*)(g_support_h +
                            (size_t)g_of_col[j] * D_OUT + coff) + lane);
            acc_half4(acc0, h, g_of_val[j]);
        }
    }

    float4 r4;
    r4.x = fmaxf(acc0[0] + acc1[0], 0.f);
    r4.y = fmaxf(acc0[1] + acc1[1], 0.f);
    r4.z = fmaxf(acc0[2] + acc1[2], 0.f);
    r4.w = fmaxf(acc0[3] + acc1[3], 0.f);
    __stcs((float4*)(out + (size_t)row * D_OUT + coff) + lane, r4);
}

// ---------------------------------------------------------------------------
// Launch: priorities INVERTED vs R11 —
//   S4 (HIGH prio, small grid): GEMM-B — wins SM slots at GEMM-A completion,
//       co-resides with rowaccA instead of waiting for it to drain.
//   S3 (normal): rowaccA fills remaining slots.
//   S0: GEMM-A -> rowaccB(waits GEMM-B+bucket) ;  S2: detect -> bucket
// ---------------------------------------------------------------------------
extern "C" void kernel_launch(void* const* d_in, const int* in_sizes, int n_in,
                              void* d_out, int out_size)
{
    static cudaStream_t s2 = nullptr, s3 = nullptr, s4 = nullptr;
    static cudaEvent_t ev_fork = nullptr, ev_csr = nullptr,
                       ev_ga = nullptr, ev_gb = nullptr, ev_ra = nullptr;
    static bool tried = false;
    if (!tried) {
        tried = true;
        int lo = 0, hi = 0;
        cudaDeviceGetStreamPriorityRange(&lo, &hi);
        bool ok = cudaStreamCreateWithPriority(&s2, cudaStreamNonBlocking, 0) == cudaSuccess
               && cudaStreamCreateWithPriority(&s3, cudaStreamNonBlocking, 0) == cudaSuccess
               && cudaStreamCreateWithPriority(&s4, cudaStreamNonBlocking, hi) == cudaSuccess
               && cudaEventCreateWithFlags(&ev_fork, cudaEventDisableTiming) == cudaSuccess
               && cudaEventCreateWithFlags(&ev_csr,  cudaEventDisableTiming) == cudaSuccess
               && cudaEventCreateWithFlags(&ev_ga,   cudaEventDisableTiming) == cudaSuccess
               && cudaEventCreateWithFlags(&ev_gb,   cudaEventDisableTiming) == cudaSuccess
               && cudaEventCreateWithFlags(&ev_ra,   cudaEventDisableTiming) == cudaSuccess;
        if (!ok) s2 = nullptr;
        cudaFuncSetAttribute(gemm_tf32_kernel,
                             cudaFuncAttributeMaxDynamicSharedMemorySize,
                             GEMM_SMEM_BYTES);
    }
    const bool par = (s2 != nullptr);
    cudaStream_t cs = par ? s2 : DEF_STREAM;

    const float* features = (const float*)d_in[0];
    const float* weight   = (const float*)d_in[1];
    const void*  adj_row  = d_in[2];
    const void*  adj_col  = d_in[3];
    const float* adj_val  = (const float*)d_in[4];
    float* out = (float*)d_out;

    const int n_nodes = in_sizes[0] / D_IN;
    const int n_edges = in_sizes[4];

    if (par) {
        cudaEventRecord(ev_fork, DEF_STREAM);
        cudaStreamWaitEvent(s2, ev_fork, 0);
    }

    // --- S2: detect + zero cursors, then coalesced bucketing ---
    detect_zero_kernel<<<(n_nodes + 255) / 256, 256, 0, cs>>>(
        (const unsigned int*)adj_row, n_nodes);
    bucket_kernel<<<(n_edges + 255) / 256, 256, 0, cs>>>(adj_row, adj_col,
                                                         adj_val, n_edges);
    if (par) cudaEventRecord(ev_csr, s2);

    // --- S0: GEMM-A (support cols 0-127), starts immediately ---
    dim3 ggrid(1, (n_nodes + GM - 1) / GM);
    gemm_tf32_kernel<<<ggrid, 256, GEMM_SMEM_BYTES>>>(features, weight,
                                                      n_nodes, 0);
    if (par) cudaEventRecord(ev_ga, DEF_STREAM);

    if (par) {
        // --- S4 (HIGH priority, enqueued first): GEMM-B after GEMM-A ---
        cudaStreamWaitEvent(s4, ev_ga, 0);
        gemm_tf32_kernel<<<ggrid, 256, GEMM_SMEM_BYTES, s4>>>(features, weight,
                                                              n_nodes, 128);
        cudaEventRecord(ev_gb, s4);

        // --- S3 (normal priority): rowaccA after GEMM-A + bucket,
        //     co-resident with GEMM-B ---
        cudaStreamWaitEvent(s3, ev_ga, 0);
        cudaStreamWaitEvent(s3, ev_csr, 0);
        rowacc_kernel<<<(n_nodes + 7) / 8, 256, 0, s3>>>(out, n_nodes, 0);
        cudaEventRecord(ev_ra, s3);

        // --- S0: rowaccB after GEMM-B + bucket ---
        cudaStreamWaitEvent(DEF_STREAM, ev_gb, 0);
        cudaStreamWaitEvent(DEF_STREAM, ev_csr, 0);
        rowacc_kernel<<<(n_nodes + 7) / 8, 256>>>(out, n_nodes, 128);

        cudaStreamWaitEvent(DEF_STREAM, ev_ra, 0);
    } else {
        // Fallback: fully serial on default stream
        gemm_tf32_kernel<<<ggrid, 256, GEMM_SMEM_BYTES>>>(features, weight,
                                                          n_nodes, 128);
        rowacc_kernel<<<(n_nodes + 7) / 8, 256>>>(out, n_nodes, 0);
        rowacc_kernel<<<(n_nodes + 7) / 8, 256>>>(out, n_nodes, 128);
    }
}